// round 1
// baseline (speedup 1.0000x reference)
#include <cuda_runtime.h>

// Shapes (fixed for this problem)
//  B=2, D=H=W=64, L=262144, C=64, WS=2, S=8, NH=8, HD=8, MLP=256
//  windows per batch: 32*32*32 = 32768; total windows = 65536

__device__ __forceinline__ int rid_(int c) { return c < 62 ? 0 : (c == 62 ? 1 : 2); }

__global__ void __launch_bounds__(256) swin_attn_kernel(
    const float* __restrict__ x,
    const float* __restrict__ n1g, const float* __restrict__ n1b,
    const float* __restrict__ qkvw, const float* __restrict__ qkvb,
    const float* __restrict__ rpb,
    const float* __restrict__ projw, const float* __restrict__ projb,
    float* __restrict__ x1)
{
    __shared__ float s_buf[4][8][64];     // xn, later reused as attn_out
    __shared__ float s_qkv[4][8][193];    // q | k | v per token (padded stride)
    __shared__ float s_mu[4][8];
    __shared__ float s_rs[4][8];

    const int w   = threadIdx.x >> 6;     // window slot in block
    const int t   = threadIdx.x & 63;     // channel / lane role
    const int gw  = (blockIdx.x << 2) + w;
    const int bb  = gw >> 15;             // batch
    const int win = gw & 32767;
    const int pz = win >> 10, py = (win >> 5) & 31, px = win & 31;
    const int xbase = bb << 24;           // b * L * C

    // ---- Phase 1: shifted gather + LayerNorm1 ----
    float raw[8];
#pragma unroll
    for (int s = 0; s < 8; ++s) {
        int dz = ((pz << 1) + (s >> 2) + 1) & 63;
        int dy = ((py << 1) + ((s >> 1) & 1) + 1) & 63;
        int dx = ((px << 1) + (s & 1) + 1) & 63;
        int l  = (dz << 12) | (dy << 6) | dx;
        raw[s] = x[xbase + (l << 6) + t];
        s_buf[w][s][t] = raw[s];
    }
    __syncthreads();
    if (t < 8) {
        float sum = 0.f, sq = 0.f;
#pragma unroll
        for (int c = 0; c < 64; ++c) { float v = s_buf[w][t][c]; sum += v; sq += v * v; }
        float mu  = sum * 0.015625f;
        float var = fmaxf(sq * 0.015625f - mu * mu, 0.f);
        s_mu[w][t] = mu;
        s_rs[w][t] = rsqrtf(var + 1e-5f);
    }
    __syncthreads();
    {
        float gg = n1g[t], be = n1b[t];
#pragma unroll
        for (int s = 0; s < 8; ++s)
            s_buf[w][s][t] = (raw[s] - s_mu[w][s]) * s_rs[w][s] * gg + be;
    }
    __syncthreads();

    // ---- Phase 2: QKV (8x64 @ 64x192) ----
    {
        float aq[8], ak[8], av[8];
#pragma unroll
        for (int s = 0; s < 8; ++s) { aq[s] = 0.f; ak[s] = 0.f; av[s] = 0.f; }
#pragma unroll 4
        for (int c = 0; c < 64; ++c) {
            float wq = __ldg(qkvw + c * 192 + t);
            float wk = __ldg(qkvw + c * 192 + 64 + t);
            float wv = __ldg(qkvw + c * 192 + 128 + t);
#pragma unroll
            for (int s = 0; s < 8; ++s) {
                float xv = s_buf[w][s][c];
                aq[s] = fmaf(xv, wq, aq[s]);
                ak[s] = fmaf(xv, wk, ak[s]);
                av[s] = fmaf(xv, wv, av[s]);
            }
        }
        const float scale = 0.35355339059327373f;   // (C/NH)^-0.5 = 8^-0.5
        float bq = qkvb[t], bk = qkvb[64 + t], bv = qkvb[128 + t];
#pragma unroll
        for (int s = 0; s < 8; ++s) {
            s_qkv[w][s][t]       = (aq[s] + bq) * scale;
            s_qkv[w][s][64 + t]  = ak[s] + bk;
            s_qkv[w][s][128 + t] = av[s] + bv;
        }
    }
    __syncthreads();

    // ---- Phase 3: attention, thread = (head hh, query qi) ----
    {
        const int hh = t >> 3, qi = t & 7;
        float q[8];
#pragma unroll
        for (int d = 0; d < 8; ++d) q[d] = s_qkv[w][qi][hh * 8 + d];

        // boundary mask region ids (shifted-frame coordinates)
        int mv[8];
#pragma unroll
        for (int s = 0; s < 8; ++s) {
            int rz = rid_((pz << 1) + (s >> 2));
            int ry = rid_((py << 1) + ((s >> 1) & 1));
            int rx = rid_((px << 1) + (s & 1));
            mv[s] = rz * 9 + ry * 3 + rx;
        }
        const int mi = mv[qi];

        // bug-faithful relative position bias: bias(h,i,j) = rpb[RELIDX(h,i)*8 + j]
        // RELIDX via np.meshgrid 'xy' quirk: cf0=bit1, cf1=bit2, cf2=bit0
        const int cf0p = (hh >> 1) & 1, cf1p = hh >> 2, cf2p = hh & 1;
        const int cf0q = (qi >> 1) & 1, cf1q = qi >> 2, cf2q = qi & 1;
        const int ridx = 3 * (cf0p - cf0q + 1) + (cf1p - cf1q + 1) + (cf2p - cf2q + 1);

        float sc[8];
#pragma unroll
        for (int j = 0; j < 8; ++j) {
            float a = 0.f;
#pragma unroll
            for (int d = 0; d < 8; ++d)
                a = fmaf(q[d], s_qkv[w][j][64 + hh * 8 + d], a);
            a += __ldg(rpb + ridx * 8 + j);
            if (mv[j] != mi) a -= 100.f;
            sc[j] = a;
        }
        float mx = sc[0];
#pragma unroll
        for (int j = 1; j < 8; ++j) mx = fmaxf(mx, sc[j]);
        float den = 0.f;
#pragma unroll
        for (int j = 0; j < 8; ++j) { sc[j] = __expf(sc[j] - mx); den += sc[j]; }
        float inv = 1.f / den;
#pragma unroll
        for (int j = 0; j < 8; ++j) sc[j] *= inv;

        // out[i][h*8+d] = sum_j p[j] * v[j][h*8+d]   (xn in s_buf is dead -> reuse)
#pragma unroll
        for (int d = 0; d < 8; ++d) {
            float o = 0.f;
#pragma unroll
            for (int j = 0; j < 8; ++j)
                o = fmaf(sc[j], s_qkv[w][j][128 + hh * 8 + d], o);
            s_buf[w][qi][hh * 8 + d] = o;
        }
    }
    __syncthreads();

    // ---- Phase 4: proj + bug-faithful window-reverse + roll(+1) + residual ----
    {
        float acc[8];
#pragma unroll
        for (int s = 0; s < 8; ++s) acc[s] = 0.f;
#pragma unroll 4
        for (int c = 0; c < 64; ++c) {
            float wp = __ldg(projw + c * 64 + t);
#pragma unroll
            for (int s = 0; s < 8; ++s)
                acc[s] = fmaf(s_buf[w][s][c], wp, acc[s]);
        }
        float pb = projb[t];
#pragma unroll
        for (int s = 0; s < 8; ++s) {
            // t_flat = pz<<13 | py<<8 | px<<3 | s, reinterpreted as
            // (pz1, a, py1, px1, b2, c2) with sizes (32,2,32,32,2,2), then
            // transpose -> g = ((((pz1*32+py1)*2+b2)*2+a)*32+px1)*2+c2
            int px1 = ((px & 15) << 1) | (s >> 2);
            int py1 = ((py & 15) << 1) | (px >> 4);
            int a2  = (py >> 4) & 1;
            int b2  = (s >> 1) & 1;
            int c2  = s & 1;
            int g = (pz << 5) + py1;
            g = (g << 1) + b2;
            g = (g << 1) + a2;
            g = (g << 5) + px1;
            g = (g << 1) + c2;
            int dd  = ((g >> 12) + 1) & 63;
            int hh2 = ((g >> 6) + 1) & 63;
            int ww2 = (g + 1) & 63;
            int lf  = (dd << 12) | (hh2 << 6) | ww2;
            int off = xbase + (lf << 6) + t;
            x1[off] = acc[s] + pb + x[off];
        }
    }
}

__global__ void __launch_bounds__(256) swin_mlp_kernel(
    float* io,                            // x1 in, final out in-place
    const float* __restrict__ n2g, const float* __restrict__ n2b,
    const float* __restrict__ w1, const float* __restrict__ b1,
    const float* __restrict__ w2, const float* __restrict__ b2)
{
    __shared__ float s_xr[16][64];
    __shared__ float s_xn[16][64];
    __shared__ float s_h1[16][256];
    __shared__ float s_mu[16], s_rs[16];

    const int tid  = threadIdx.x;
    const int base = blockIdx.x * (16 * 64);

    for (int idx = tid; idx < 1024; idx += 256)
        s_xr[idx >> 6][idx & 63] = io[base + idx];
    __syncthreads();
    if (tid < 16) {
        float sum = 0.f, sq = 0.f;
#pragma unroll
        for (int c = 0; c < 64; ++c) { float v = s_xr[tid][c]; sum += v; sq += v * v; }
        float mu  = sum * 0.015625f;
        float var = fmaxf(sq * 0.015625f - mu * mu, 0.f);
        s_mu[tid] = mu;
        s_rs[tid] = rsqrtf(var + 1e-5f);
    }
    __syncthreads();
    for (int idx = tid; idx < 1024; idx += 256) {
        int s = idx >> 6, c = idx & 63;
        s_xn[s][c] = (s_xr[s][c] - s_mu[s]) * s_rs[s] * n2g[c] + n2b[c];
    }
    __syncthreads();

    // GEMM1: hidden unit j = tid over 16 tokens, exact GELU
    {
        float acc[16];
#pragma unroll
        for (int s = 0; s < 16; ++s) acc[s] = 0.f;
#pragma unroll 2
        for (int c = 0; c < 64; c += 4) {
            float wa = __ldg(w1 + (c    ) * 256 + tid);
            float wb = __ldg(w1 + (c + 1) * 256 + tid);
            float wc = __ldg(w1 + (c + 2) * 256 + tid);
            float wd = __ldg(w1 + (c + 3) * 256 + tid);
#pragma unroll
            for (int s = 0; s < 16; ++s) {
                float4 xv = *reinterpret_cast<const float4*>(&s_xn[s][c]);
                acc[s] = fmaf(xv.x, wa, acc[s]);
                acc[s] = fmaf(xv.y, wb, acc[s]);
                acc[s] = fmaf(xv.z, wc, acc[s]);
                acc[s] = fmaf(xv.w, wd, acc[s]);
            }
        }
        float bias = b1[tid];
#pragma unroll
        for (int s = 0; s < 16; ++s) {
            float h = acc[s] + bias;
            s_h1[s][tid] = 0.5f * h * (1.f + erff(h * 0.70710678118654752f));
        }
    }
    __syncthreads();

    // GEMM2: thread -> (cout = tid&63, 4 tokens), + bias + residual
    {
        const int cout = tid & 63;
        const int sg   = (tid >> 6) << 2;
        float acc[4] = {0.f, 0.f, 0.f, 0.f};
#pragma unroll 2
        for (int j = 0; j < 256; j += 4) {
            float wa = __ldg(w2 + (j    ) * 64 + cout);
            float wb = __ldg(w2 + (j + 1) * 64 + cout);
            float wc = __ldg(w2 + (j + 2) * 64 + cout);
            float wd = __ldg(w2 + (j + 3) * 64 + cout);
#pragma unroll
            for (int k = 0; k < 4; ++k) {
                float4 h4 = *reinterpret_cast<const float4*>(&s_h1[sg + k][j]);
                acc[k] = fmaf(h4.x, wa, acc[k]);
                acc[k] = fmaf(h4.y, wb, acc[k]);
                acc[k] = fmaf(h4.z, wc, acc[k]);
                acc[k] = fmaf(h4.w, wd, acc[k]);
            }
        }
        float bias = b2[cout];
#pragma unroll
        for (int k = 0; k < 4; ++k) {
            int s = sg + k;
            io[base + s * 64 + cout] = acc[k] + bias + s_xr[s][cout];
        }
    }
}

extern "C" void kernel_launch(void* const* d_in, const int* in_sizes, int n_in,
                              void* d_out, int out_size)
{
    const float* x     = (const float*)d_in[0];
    const float* n1g   = (const float*)d_in[1];
    const float* n1b   = (const float*)d_in[2];
    const float* qkvw  = (const float*)d_in[3];
    const float* qkvb  = (const float*)d_in[4];
    const float* rpb   = (const float*)d_in[5];
    const float* projw = (const float*)d_in[6];
    const float* projb = (const float*)d_in[7];
    const float* n2g   = (const float*)d_in[8];
    const float* n2b   = (const float*)d_in[9];
    const float* w1    = (const float*)d_in[10];
    const float* b1    = (const float*)d_in[11];
    const float* w2    = (const float*)d_in[12];
    const float* b2    = (const float*)d_in[13];
    float* out = (float*)d_out;

    // 65536 windows, 4 per block
    swin_attn_kernel<<<16384, 256>>>(x, n1g, n1b, qkvw, qkvb, rpb, projw, projb, out);
    // 524288 tokens, 16 per block (in-place on out)
    swin_mlp_kernel<<<32768, 256>>>(out, n2g, n2b, w1, b1, w2, b2);
}

// round 2
// speedup vs baseline: 1.9096x; 1.9096x over previous
#include <cuda_runtime.h>
#include <cstdint>

// Shapes (fixed): B=2, D=H=W=64, L=262144, C=64, WS=2, S=8, NH=8, HD=8, MLP=256

__device__ __forceinline__ int rid_(int c) { return c < 62 ? 0 : (c == 62 ? 1 : 2); }

// ---------------------------------------------------------------------------
// Attention kernel (unchanged from R1 — tensorize next round)
// ---------------------------------------------------------------------------
__global__ void __launch_bounds__(256) swin_attn_kernel(
    const float* __restrict__ x,
    const float* __restrict__ n1g, const float* __restrict__ n1b,
    const float* __restrict__ qkvw, const float* __restrict__ qkvb,
    const float* __restrict__ rpb,
    const float* __restrict__ projw, const float* __restrict__ projb,
    float* __restrict__ x1)
{
    __shared__ float s_buf[4][8][64];
    __shared__ float s_qkv[4][8][193];
    __shared__ float s_mu[4][8];
    __shared__ float s_rs[4][8];

    const int w   = threadIdx.x >> 6;
    const int t   = threadIdx.x & 63;
    const int gw  = (blockIdx.x << 2) + w;
    const int bb  = gw >> 15;
    const int win = gw & 32767;
    const int pz = win >> 10, py = (win >> 5) & 31, px = win & 31;
    const int xbase = bb << 24;

    float raw[8];
#pragma unroll
    for (int s = 0; s < 8; ++s) {
        int dz = ((pz << 1) + (s >> 2) + 1) & 63;
        int dy = ((py << 1) + ((s >> 1) & 1) + 1) & 63;
        int dx = ((px << 1) + (s & 1) + 1) & 63;
        int l  = (dz << 12) | (dy << 6) | dx;
        raw[s] = x[xbase + (l << 6) + t];
        s_buf[w][s][t] = raw[s];
    }
    __syncthreads();
    if (t < 8) {
        float sum = 0.f, sq = 0.f;
#pragma unroll
        for (int c = 0; c < 64; ++c) { float v = s_buf[w][t][c]; sum += v; sq += v * v; }
        float mu  = sum * 0.015625f;
        float var = fmaxf(sq * 0.015625f - mu * mu, 0.f);
        s_mu[w][t] = mu;
        s_rs[w][t] = rsqrtf(var + 1e-5f);
    }
    __syncthreads();
    {
        float gg = n1g[t], be = n1b[t];
#pragma unroll
        for (int s = 0; s < 8; ++s)
            s_buf[w][s][t] = (raw[s] - s_mu[w][s]) * s_rs[w][s] * gg + be;
    }
    __syncthreads();

    {
        float aq[8], ak[8], av[8];
#pragma unroll
        for (int s = 0; s < 8; ++s) { aq[s] = 0.f; ak[s] = 0.f; av[s] = 0.f; }
#pragma unroll 4
        for (int c = 0; c < 64; ++c) {
            float wq = __ldg(qkvw + c * 192 + t);
            float wk = __ldg(qkvw + c * 192 + 64 + t);
            float wv = __ldg(qkvw + c * 192 + 128 + t);
#pragma unroll
            for (int s = 0; s < 8; ++s) {
                float xv = s_buf[w][s][c];
                aq[s] = fmaf(xv, wq, aq[s]);
                ak[s] = fmaf(xv, wk, ak[s]);
                av[s] = fmaf(xv, wv, av[s]);
            }
        }
        const float scale = 0.35355339059327373f;
        float bq = qkvb[t], bk = qkvb[64 + t], bv = qkvb[128 + t];
#pragma unroll
        for (int s = 0; s < 8; ++s) {
            s_qkv[w][s][t]       = (aq[s] + bq) * scale;
            s_qkv[w][s][64 + t]  = ak[s] + bk;
            s_qkv[w][s][128 + t] = av[s] + bv;
        }
    }
    __syncthreads();

    {
        const int hh = t >> 3, qi = t & 7;
        float q[8];
#pragma unroll
        for (int d = 0; d < 8; ++d) q[d] = s_qkv[w][qi][hh * 8 + d];

        int mv[8];
#pragma unroll
        for (int s = 0; s < 8; ++s) {
            int rz = rid_((pz << 1) + (s >> 2));
            int ry = rid_((py << 1) + ((s >> 1) & 1));
            int rx = rid_((px << 1) + (s & 1));
            mv[s] = rz * 9 + ry * 3 + rx;
        }
        const int mi = mv[qi];

        const int cf0p = (hh >> 1) & 1, cf1p = hh >> 2, cf2p = hh & 1;
        const int cf0q = (qi >> 1) & 1, cf1q = qi >> 2, cf2q = qi & 1;
        const int ridx = 3 * (cf0p - cf0q + 1) + (cf1p - cf1q + 1) + (cf2p - cf2q + 1);

        float sc[8];
#pragma unroll
        for (int j = 0; j < 8; ++j) {
            float a = 0.f;
#pragma unroll
            for (int d = 0; d < 8; ++d)
                a = fmaf(q[d], s_qkv[w][j][64 + hh * 8 + d], a);
            a += __ldg(rpb + ridx * 8 + j);
            if (mv[j] != mi) a -= 100.f;
            sc[j] = a;
        }
        float mx = sc[0];
#pragma unroll
        for (int j = 1; j < 8; ++j) mx = fmaxf(mx, sc[j]);
        float den = 0.f;
#pragma unroll
        for (int j = 0; j < 8; ++j) { sc[j] = __expf(sc[j] - mx); den += sc[j]; }
        float inv = 1.f / den;
#pragma unroll
        for (int j = 0; j < 8; ++j) sc[j] *= inv;

#pragma unroll
        for (int d = 0; d < 8; ++d) {
            float o = 0.f;
#pragma unroll
            for (int j = 0; j < 8; ++j)
                o = fmaf(sc[j], s_qkv[w][j][128 + hh * 8 + d], o);
            s_buf[w][qi][hh * 8 + d] = o;
        }
    }
    __syncthreads();

    {
        float acc[8];
#pragma unroll
        for (int s = 0; s < 8; ++s) acc[s] = 0.f;
#pragma unroll 4
        for (int c = 0; c < 64; ++c) {
            float wp = __ldg(projw + c * 64 + t);
#pragma unroll
            for (int s = 0; s < 8; ++s)
                acc[s] = fmaf(s_buf[w][s][c], wp, acc[s]);
        }
        float pb = projb[t];
#pragma unroll
        for (int s = 0; s < 8; ++s) {
            int px1 = ((px & 15) << 1) | (s >> 2);
            int py1 = ((py & 15) << 1) | (px >> 4);
            int a2  = (py >> 4) & 1;
            int b2  = (s >> 1) & 1;
            int c2  = s & 1;
            int g = (pz << 5) + py1;
            g = (g << 1) + b2;
            g = (g << 1) + a2;
            g = (g << 5) + px1;
            g = (g << 1) + c2;
            int dd  = ((g >> 12) + 1) & 63;
            int hh2 = ((g >> 6) + 1) & 63;
            int ww2 = (g + 1) & 63;
            int lf  = (dd << 12) | (hh2 << 6) | ww2;
            int off = xbase + (lf << 6) + t;
            x1[off] = acc[s] + pb + x[off];
        }
    }
}

// ---------------------------------------------------------------------------
// MLP kernel v2: tf32 mma.sync tensor cores
// ---------------------------------------------------------------------------
__device__ __forceinline__ uint32_t f2tf32(float f) {
    uint32_t u;
    asm("cvt.rna.tf32.f32 %0, %1;" : "=r"(u) : "f"(f));
    return u;
}

__device__ __forceinline__ void mma8(float* d, const uint32_t* a, const uint32_t* b) {
    asm volatile(
        "mma.sync.aligned.m16n8k8.row.col.f32.tf32.tf32.f32 "
        "{%0,%1,%2,%3},{%4,%5,%6,%7},{%8,%9},{%0,%1,%2,%3};\n"
        : "+f"(d[0]), "+f"(d[1]), "+f"(d[2]), "+f"(d[3])
        : "r"(a[0]), "r"(a[1]), "r"(a[2]), "r"(a[3]), "r"(b[0]), "r"(b[1]));
}

__device__ __forceinline__ float gelu_exact(float h) {
    return 0.5f * h * (1.f + erff(h * 0.70710678118654752f));
}

__global__ void __launch_bounds__(128) swin_mlp_tc_kernel(
    float* __restrict__ io,
    const float* __restrict__ n2g, const float* __restrict__ n2b,
    const float* __restrict__ w1, const float* __restrict__ b1,
    const float* __restrict__ w2, const float* __restrict__ b2)
{
    // swizzles: s_a/s_h element (m,k) at m*64 + (k ^ (4*(m&7)))
    //           s_w  element (k,n) at k*64 + (n ^ (8*(k&3)))
    __shared__ uint32_t s_a[64 * 64];
    __shared__ uint32_t s_h[64 * 64];
    __shared__ uint32_t s_w[64 * 64];

    const int tid  = threadIdx.x;
    const int lane = tid & 31;
    const int wrp  = tid >> 5;
    const int g    = lane >> 2, tg = lane & 3;
    const int wm   = wrp & 1, wn = wrp >> 1;       // warp tile: rows 32*wm, cols 32*wn
    const int base = blockIdx.x * 4096;            // 64 tokens * 64 ch

    // ---- Phase 1: load + LayerNorm2 (shuffle-only) + tf32 into s_a ----
    const int q = tid & 15;                        // float4 column slot (constant)
    const float4 gam = *(const float4*)(n2g + q * 4);
    const float4 bet = *(const float4*)(n2b + q * 4);
#pragma unroll
    for (int p = 0; p < 8; ++p) {
        int m = p * 8 + (tid >> 4);
        float4 v = *(const float4*)(io + base + m * 64 + q * 4);
        float s  = v.x + v.y + v.z + v.w;
        float ss = v.x * v.x + v.y * v.y + v.z * v.z + v.w * v.w;
#pragma unroll
        for (int o = 8; o; o >>= 1) {
            s  += __shfl_xor_sync(0xffffffffu, s, o);
            ss += __shfl_xor_sync(0xffffffffu, ss, o);
        }
        float mu = s * 0.015625f;
        float rs = rsqrtf(fmaxf(ss * 0.015625f - mu * mu, 0.f) + 1e-5f);
        uint4 o4;
        o4.x = f2tf32((v.x - mu) * rs * gam.x + bet.x);
        o4.y = f2tf32((v.y - mu) * rs * gam.y + bet.y);
        o4.z = f2tf32((v.z - mu) * rs * gam.z + bet.z);
        o4.w = f2tf32((v.w - mu) * rs * gam.w + bet.w);
        *(uint4*)&s_a[m * 64 + ((q * 4) ^ (4 * (m & 7)))] = o4;
    }
    __syncthreads();

    float c2[2][4][4];
#pragma unroll
    for (int i = 0; i < 2; ++i)
#pragma unroll
        for (int j = 0; j < 4; ++j)
#pragma unroll
            for (int r = 0; r < 4; ++r) c2[i][j][r] = 0.f;

    for (int nc = 0; nc < 4; ++nc) {
        // ---- stage W1 chunk (64 c-rows x 64 hidden-cols) ----
#pragma unroll
        for (int p = 0; p < 8; ++p) {
            int k = p * 8 + (tid >> 4);
            float4 v = *(const float4*)(w1 + k * 256 + nc * 64 + q * 4);
            uint4 o4 = { f2tf32(v.x), f2tf32(v.y), f2tf32(v.z), f2tf32(v.w) };
            *(uint4*)&s_w[k * 64 + ((q * 4) ^ (8 * (k & 3)))] = o4;
        }
        __syncthreads();

        // ---- GEMM1: f1 = xn @ W1chunk  (warp: 32x32) ----
        float f1[2][4][4];
#pragma unroll
        for (int i = 0; i < 2; ++i)
#pragma unroll
            for (int j = 0; j < 4; ++j)
#pragma unroll
                for (int r = 0; r < 4; ++r) f1[i][j][r] = 0.f;

#pragma unroll
        for (int k0 = 0; k0 < 8; ++k0) {
            uint32_t a[2][4], b[4][2];
            int kk = k0 * 8 + tg;
#pragma unroll
            for (int i = 0; i < 2; ++i) {
                int r0 = wm * 32 + i * 16 + g;
                int r1 = r0 + 8;
                a[i][0] = s_a[r0 * 64 + (kk ^ (4 * (r0 & 7)))];
                a[i][1] = s_a[r1 * 64 + (kk ^ (4 * (r1 & 7)))];
                a[i][2] = s_a[r0 * 64 + ((kk + 4) ^ (4 * (r0 & 7)))];
                a[i][3] = s_a[r1 * 64 + ((kk + 4) ^ (4 * (r1 & 7)))];
            }
#pragma unroll
            for (int j = 0; j < 4; ++j) {
                int cn = wn * 32 + j * 8 + g;
                b[j][0] = s_w[kk * 64 + (cn ^ (8 * tg))];
                b[j][1] = s_w[(kk + 4) * 64 + (cn ^ (8 * tg))];
            }
#pragma unroll
            for (int i = 0; i < 2; ++i)
#pragma unroll
                for (int j = 0; j < 4; ++j)
                    mma8(f1[i][j], a[i], b[j]);
        }

        // ---- bias + GELU -> s_h (tf32) ----
#pragma unroll
        for (int i = 0; i < 2; ++i) {
            int m0 = wm * 32 + i * 16 + g;
            int m1 = m0 + 8;
#pragma unroll
            for (int j = 0; j < 4; ++j) {
                int col0 = wn * 32 + j * 8 + tg * 2;
                float bb0 = __ldg(b1 + nc * 64 + col0);
                float bb1 = __ldg(b1 + nc * 64 + col0 + 1);
                uint2 h0, h1;
                h0.x = f2tf32(gelu_exact(f1[i][j][0] + bb0));
                h0.y = f2tf32(gelu_exact(f1[i][j][1] + bb1));
                h1.x = f2tf32(gelu_exact(f1[i][j][2] + bb0));
                h1.y = f2tf32(gelu_exact(f1[i][j][3] + bb1));
                *(uint2*)&s_h[m0 * 64 + (col0 ^ (4 * (m0 & 7)))] = h0;
                *(uint2*)&s_h[m1 * 64 + (col0 ^ (4 * (m1 & 7)))] = h1;
            }
        }
        __syncthreads();

        // ---- stage W2 chunk (64 hidden-rows x 64 out-cols) ----
#pragma unroll
        for (int p = 0; p < 8; ++p) {
            int k = p * 8 + (tid >> 4);
            float4 v = *(const float4*)(w2 + (nc * 64 + k) * 64 + q * 4);
            uint4 o4 = { f2tf32(v.x), f2tf32(v.y), f2tf32(v.z), f2tf32(v.w) };
            *(uint4*)&s_w[k * 64 + ((q * 4) ^ (8 * (k & 3)))] = o4;
        }
        __syncthreads();

        // ---- GEMM2 partial: c2 += h @ W2chunk ----
#pragma unroll
        for (int k0 = 0; k0 < 8; ++k0) {
            uint32_t a[2][4], b[4][2];
            int kk = k0 * 8 + tg;
#pragma unroll
            for (int i = 0; i < 2; ++i) {
                int r0 = wm * 32 + i * 16 + g;
                int r1 = r0 + 8;
                a[i][0] = s_h[r0 * 64 + (kk ^ (4 * (r0 & 7)))];
                a[i][1] = s_h[r1 * 64 + (kk ^ (4 * (r1 & 7)))];
                a[i][2] = s_h[r0 * 64 + ((kk + 4) ^ (4 * (r0 & 7)))];
                a[i][3] = s_h[r1 * 64 + ((kk + 4) ^ (4 * (r1 & 7)))];
            }
#pragma unroll
            for (int j = 0; j < 4; ++j) {
                int cn = wn * 32 + j * 8 + g;
                b[j][0] = s_w[kk * 64 + (cn ^ (8 * tg))];
                b[j][1] = s_w[(kk + 4) * 64 + (cn ^ (8 * tg))];
            }
#pragma unroll
            for (int i = 0; i < 2; ++i)
#pragma unroll
                for (int j = 0; j < 4; ++j)
                    mma8(c2[i][j], a[i], b[j]);
        }
        __syncthreads();   // protect s_w/s_h for next chunk
    }

    // ---- epilogue: + b2 + residual, write back ----
#pragma unroll
    for (int i = 0; i < 2; ++i) {
        int m0 = wm * 32 + i * 16 + g;
        int m1 = m0 + 8;
#pragma unroll
        for (int j = 0; j < 4; ++j) {
            int col = wn * 32 + j * 8 + tg * 2;
            float bb0 = __ldg(b2 + col);
            float bb1 = __ldg(b2 + col + 1);
            float2 r0 = *(const float2*)(io + base + m0 * 64 + col);
            float2 r1 = *(const float2*)(io + base + m1 * 64 + col);
            float2 o0, o1;
            o0.x = c2[i][j][0] + bb0 + r0.x;
            o0.y = c2[i][j][1] + bb1 + r0.y;
            o1.x = c2[i][j][2] + bb0 + r1.x;
            o1.y = c2[i][j][3] + bb1 + r1.y;
            *(float2*)(io + base + m0 * 64 + col) = o0;
            *(float2*)(io + base + m1 * 64 + col) = o1;
        }
    }
}

extern "C" void kernel_launch(void* const* d_in, const int* in_sizes, int n_in,
                              void* d_out, int out_size)
{
    const float* x     = (const float*)d_in[0];
    const float* n1g   = (const float*)d_in[1];
    const float* n1b   = (const float*)d_in[2];
    const float* qkvw  = (const float*)d_in[3];
    const float* qkvb  = (const float*)d_in[4];
    const float* rpb   = (const float*)d_in[5];
    const float* projw = (const float*)d_in[6];
    const float* projb = (const float*)d_in[7];
    const float* n2g   = (const float*)d_in[8];
    const float* n2b   = (const float*)d_in[9];
    const float* w1    = (const float*)d_in[10];
    const float* b1    = (const float*)d_in[11];
    const float* w2    = (const float*)d_in[12];
    const float* b2    = (const float*)d_in[13];
    float* out = (float*)d_out;

    swin_attn_kernel<<<16384, 256>>>(x, n1g, n1b, qkvw, qkvb, rpb, projw, projb, out);
    swin_mlp_tc_kernel<<<8192, 128>>>(out, n2g, n2b, w1, b1, w2, b2);
}

// round 3
// speedup vs baseline: 2.8593x; 1.4973x over previous
#include <cuda_runtime.h>
#include <cstdint>

// Shapes (fixed): B=2, D=H=W=64, L=262144, C=64, WS=2, S=8, NH=8, HD=8, MLP=256

__device__ __forceinline__ int rid_(int c) { return c < 62 ? 0 : (c == 62 ? 1 : 2); }

__device__ __forceinline__ uint32_t f2tf32(float f) {
    uint32_t u;
    asm("cvt.rna.tf32.f32 %0, %1;" : "=r"(u) : "f"(f));
    return u;
}

__device__ __forceinline__ void mma8(float* d, const uint32_t* a, const uint32_t* b) {
    asm volatile(
        "mma.sync.aligned.m16n8k8.row.col.f32.tf32.tf32.f32 "
        "{%0,%1,%2,%3},{%4,%5,%6,%7},{%8,%9},{%0,%1,%2,%3};\n"
        : "+f"(d[0]), "+f"(d[1]), "+f"(d[2]), "+f"(d[3])
        : "r"(a[0]), "r"(a[1]), "r"(a[2]), "r"(a[3]), "r"(b[0]), "r"(b[1]));
}

__device__ __forceinline__ float gelu_exact(float h) {
    return 0.5f * h * (1.f + erff(h * 0.70710678118654752f));
}

// ---------------------------------------------------------------------------
// Attention kernel v2: tensor-core QKV + proj, scalar 8x8 attention core.
// Block = 8 windows = 64 tokens, 256 threads (8 warps, warp tile 16x32).
// Dynamic smem: s_a (64x64 u32 tf32 swizzled) | s_w (64x64 u32) | s_qkv (64x193 f32)
// ---------------------------------------------------------------------------
__global__ void __launch_bounds__(256) swin_attn_tc_kernel(
    const float* __restrict__ x,
    const float* __restrict__ n1g, const float* __restrict__ n1b,
    const float* __restrict__ qkvw, const float* __restrict__ qkvb,
    const float* __restrict__ rpb,
    const float* __restrict__ projw, const float* __restrict__ projb,
    float* __restrict__ x1)
{
    extern __shared__ unsigned char smem_raw[];
    uint32_t* s_a   = (uint32_t*)smem_raw;          // 4096 u32
    uint32_t* s_w   = s_a + 4096;                   // 4096 u32
    float*    s_qkv = (float*)(s_w + 4096);         // 64 * 193 f32

    const int tid  = threadIdx.x;
    const int lane = tid & 31;
    const int wrp  = tid >> 5;
    const int g    = lane >> 2, tg = lane & 3;
    const int R    = (wrp & 3) << 4;                // warp row base (16)
    const int Cb   = (wrp >> 2) << 5;               // warp col base (32)

    // ---- Phase 1: shifted gather + LayerNorm1 -> s_a (tf32 swizzled) ----
    {
        const int m  = tid >> 2;                    // token 0..63
        const int cq = (tid & 3) << 4;              // channel base (16 ch)
        const int gwin = blockIdx.x * 8 + (m >> 3);
        const int bb   = gwin >> 15;
        const int w15  = gwin & 32767;
        const int pz = w15 >> 10, py = (w15 >> 5) & 31, px = w15 & 31;
        const int s = m & 7;
        const int dz = ((pz << 1) + (s >> 2) + 1) & 63;
        const int dy = ((py << 1) + ((s >> 1) & 1) + 1) & 63;
        const int dx = ((px << 1) + (s & 1) + 1) & 63;
        const float* src = x + (bb << 24) + ((((dz << 12) | (dy << 6) | dx)) << 6) + cq;

        float4 v[4];
        float sm = 0.f, sq = 0.f;
#pragma unroll
        for (int f = 0; f < 4; ++f) {
            v[f] = *(const float4*)(src + f * 4);
            sm += v[f].x + v[f].y + v[f].z + v[f].w;
            sq += v[f].x * v[f].x + v[f].y * v[f].y + v[f].z * v[f].z + v[f].w * v[f].w;
        }
        sm += __shfl_xor_sync(0xffffffffu, sm, 1);
        sq += __shfl_xor_sync(0xffffffffu, sq, 1);
        sm += __shfl_xor_sync(0xffffffffu, sm, 2);
        sq += __shfl_xor_sync(0xffffffffu, sq, 2);
        float mu = sm * 0.015625f;
        float rs = rsqrtf(fmaxf(sq * 0.015625f - mu * mu, 0.f) + 1e-5f);
        const int sw = (m & 7) << 2;
#pragma unroll
        for (int f = 0; f < 4; ++f) {
            float4 ga = *(const float4*)(n1g + cq + f * 4);
            float4 be = *(const float4*)(n1b + cq + f * 4);
            uint4 o4;
            o4.x = f2tf32((v[f].x - mu) * rs * ga.x + be.x);
            o4.y = f2tf32((v[f].y - mu) * rs * ga.y + be.y);
            o4.z = f2tf32((v[f].z - mu) * rs * ga.z + be.z);
            o4.w = f2tf32((v[f].w - mu) * rs * ga.w + be.w);
            *(uint4*)&s_a[m * 64 + ((cq + f * 4) ^ sw)] = o4;
        }
    }

    // ---- Phase 2: QKV = xn @ qkvw (3 chunks of 64), tf32 mma ----
    for (int nc = 0; nc < 3; ++nc) {
        __syncthreads();
        // stage W chunk: 64 rows x 64 cols
        {
            const int q4 = tid & 15;
#pragma unroll
            for (int p = 0; p < 4; ++p) {
                int k = p * 16 + (tid >> 4);
                float4 v = *(const float4*)(qkvw + k * 192 + nc * 64 + q4 * 4);
                uint4 o4 = { f2tf32(v.x), f2tf32(v.y), f2tf32(v.z), f2tf32(v.w) };
                *(uint4*)&s_w[k * 64 + ((q4 * 4) ^ ((k & 3) << 3))] = o4;
            }
        }
        __syncthreads();

        float f1[4][4];
#pragma unroll
        for (int j = 0; j < 4; ++j)
#pragma unroll
            for (int r = 0; r < 4; ++r) f1[j][r] = 0.f;

#pragma unroll
        for (int k0 = 0; k0 < 8; ++k0) {
            const int kk = k0 * 8 + tg;
            uint32_t a[4], b[4][2];
            {
                int r0 = R + g, r1 = r0 + 8;
                a[0] = s_a[r0 * 64 + (kk ^ ((r0 & 7) << 2))];
                a[1] = s_a[r1 * 64 + (kk ^ ((r1 & 7) << 2))];
                a[2] = s_a[r0 * 64 + ((kk + 4) ^ ((r0 & 7) << 2))];
                a[3] = s_a[r1 * 64 + ((kk + 4) ^ ((r1 & 7) << 2))];
            }
#pragma unroll
            for (int j = 0; j < 4; ++j) {
                int cn = Cb + j * 8 + g;
                b[j][0] = s_w[kk * 64 + (cn ^ (tg << 3))];
                b[j][1] = s_w[(kk + 4) * 64 + (cn ^ (tg << 3))];
            }
#pragma unroll
            for (int j = 0; j < 4; ++j) mma8(f1[j], a, b[j]);
        }

        // epilogue: +bias (scale if q-chunk) -> s_qkv fp32, stride 193
        {
            const float scale = (nc == 0) ? 0.35355339059327373f : 1.0f;
            const int m0 = R + g, m1 = m0 + 8;
#pragma unroll
            for (int j = 0; j < 4; ++j) {
                int col = Cb + j * 8 + tg * 2;
                float b0 = __ldg(qkvb + nc * 64 + col);
                float b1 = __ldg(qkvb + nc * 64 + col + 1);
                s_qkv[m0 * 193 + nc * 64 + col]     = (f1[j][0] + b0) * scale;
                s_qkv[m0 * 193 + nc * 64 + col + 1] = (f1[j][1] + b1) * scale;
                s_qkv[m1 * 193 + nc * 64 + col]     = (f1[j][2] + b0) * scale;
                s_qkv[m1 * 193 + nc * 64 + col + 1] = (f1[j][3] + b1) * scale;
            }
        }
    }
    __syncthreads();

    // ---- Phase 3: scalar attention, 512 (win,head,query) tasks / 256 thr ----
#pragma unroll
    for (int r = 0; r < 2; ++r) {
        const int tk  = tid + r * 256;
        const int win = tk >> 6, hh = (tk >> 3) & 7, qi = tk & 7;
        const int gwin = blockIdx.x * 8 + win;
        const int w15  = gwin & 32767;
        const int pz = w15 >> 10, py = (w15 >> 5) & 31, px = w15 & 31;

        float q[8];
#pragma unroll
        for (int d = 0; d < 8; ++d) q[d] = s_qkv[(win * 8 + qi) * 193 + hh * 8 + d];

        int mv[8];
#pragma unroll
        for (int s = 0; s < 8; ++s) {
            int rz = rid_((pz << 1) + (s >> 2));
            int ry = rid_((py << 1) + ((s >> 1) & 1));
            int rx = rid_((px << 1) + (s & 1));
            mv[s] = rz * 9 + ry * 3 + rx;
        }
        const int mi = mv[qi];

        const int cf0p = (hh >> 1) & 1, cf1p = hh >> 2, cf2p = hh & 1;
        const int cf0q = (qi >> 1) & 1, cf1q = qi >> 2, cf2q = qi & 1;
        const int ridx = 3 * (cf0p - cf0q + 1) + (cf1p - cf1q + 1) + (cf2p - cf2q + 1);

        float sc[8];
#pragma unroll
        for (int j = 0; j < 8; ++j) {
            float a = 0.f;
#pragma unroll
            for (int d = 0; d < 8; ++d)
                a = fmaf(q[d], s_qkv[(win * 8 + j) * 193 + 64 + hh * 8 + d], a);
            a += __ldg(rpb + ridx * 8 + j);
            if (mv[j] != mi) a -= 100.f;
            sc[j] = a;
        }
        float mx = sc[0];
#pragma unroll
        for (int j = 1; j < 8; ++j) mx = fmaxf(mx, sc[j]);
        float den = 0.f;
#pragma unroll
        for (int j = 0; j < 8; ++j) { sc[j] = __expf(sc[j] - mx); den += sc[j]; }
        float inv = 1.f / den;
#pragma unroll
        for (int j = 0; j < 8; ++j) sc[j] *= inv;

        const int m = win * 8 + qi;
        const int swz = qi << 2;
#pragma unroll
        for (int d = 0; d < 8; ++d) {
            float o = 0.f;
#pragma unroll
            for (int j = 0; j < 8; ++j)
                o = fmaf(sc[j], s_qkv[(win * 8 + j) * 193 + 128 + hh * 8 + d], o);
            s_a[m * 64 + ((hh * 8 + d) ^ swz)] = f2tf32(o);
        }
    }

    // stage proj weights (s_w free: all GEMM reads completed before last sync)
    {
        const int q4 = tid & 15;
#pragma unroll
        for (int p = 0; p < 4; ++p) {
            int k = p * 16 + (tid >> 4);
            float4 v = *(const float4*)(projw + k * 64 + q4 * 4);
            uint4 o4 = { f2tf32(v.x), f2tf32(v.y), f2tf32(v.z), f2tf32(v.w) };
            *(uint4*)&s_w[k * 64 + ((q4 * 4) ^ ((k & 3) << 3))] = o4;
        }
    }
    __syncthreads();

    // ---- Phase 4: proj GEMM + window-reverse scatter + residual ----
    {
        float c2[4][4];
#pragma unroll
        for (int j = 0; j < 4; ++j)
#pragma unroll
            for (int r = 0; r < 4; ++r) c2[j][r] = 0.f;

#pragma unroll
        for (int k0 = 0; k0 < 8; ++k0) {
            const int kk = k0 * 8 + tg;
            uint32_t a[4], b[4][2];
            {
                int r0 = R + g, r1 = r0 + 8;
                a[0] = s_a[r0 * 64 + (kk ^ ((r0 & 7) << 2))];
                a[1] = s_a[r1 * 64 + (kk ^ ((r1 & 7) << 2))];
                a[2] = s_a[r0 * 64 + ((kk + 4) ^ ((r0 & 7) << 2))];
                a[3] = s_a[r1 * 64 + ((kk + 4) ^ ((r1 & 7) << 2))];
            }
#pragma unroll
            for (int j = 0; j < 4; ++j) {
                int cn = Cb + j * 8 + g;
                b[j][0] = s_w[kk * 64 + (cn ^ (tg << 3))];
                b[j][1] = s_w[(kk + 4) * 64 + (cn ^ (tg << 3))];
            }
#pragma unroll
            for (int j = 0; j < 4; ++j) mma8(c2[j], a, b[j]);
        }

        // scatter: token m -> bug-faithful window-reverse + roll(+1)
        int offr[2];
#pragma unroll
        for (int i = 0; i < 2; ++i) {
            int m = R + g + i * 8;
            int gwin = blockIdx.x * 8 + (m >> 3);
            int bb   = gwin >> 15;
            int w15  = gwin & 32767;
            int pz = w15 >> 10, py = (w15 >> 5) & 31, px = w15 & 31;
            int s = m & 7;
            int px1 = ((px & 15) << 1) | (s >> 2);
            int py1 = ((py & 15) << 1) | (px >> 4);
            int a2  = (py >> 4) & 1;
            int b2  = (s >> 1) & 1;
            int cc2 = s & 1;
            int gg = (pz << 5) + py1;
            gg = (gg << 1) + b2;
            gg = (gg << 1) + a2;
            gg = (gg << 5) + px1;
            gg = (gg << 1) + cc2;
            int dd  = ((gg >> 12) + 1) & 63;
            int hh2 = ((gg >> 6) + 1) & 63;
            int ww2 = (gg + 1) & 63;
            offr[i] = (bb << 24) + ((((dd << 12) | (hh2 << 6) | ww2)) << 6);
        }
#pragma unroll
        for (int j = 0; j < 4; ++j) {
            int col = Cb + j * 8 + tg * 2;
            float b0 = __ldg(projb + col);
            float b1 = __ldg(projb + col + 1);
#pragma unroll
            for (int i = 0; i < 2; ++i) {
                float2 rx = *(const float2*)(x + offr[i] + col);
                float2 o;
                o.x = c2[j][2 * i]     + b0 + rx.x;
                o.y = c2[j][2 * i + 1] + b1 + rx.y;
                *(float2*)(x1 + offr[i] + col) = o;
            }
        }
    }
}

// ---------------------------------------------------------------------------
// MLP kernel (unchanged from R2): tf32 mma tensor cores
// ---------------------------------------------------------------------------
__global__ void __launch_bounds__(128) swin_mlp_tc_kernel(
    float* __restrict__ io,
    const float* __restrict__ n2g, const float* __restrict__ n2b,
    const float* __restrict__ w1, const float* __restrict__ b1,
    const float* __restrict__ w2, const float* __restrict__ b2)
{
    __shared__ uint32_t s_a[64 * 64];
    __shared__ uint32_t s_h[64 * 64];
    __shared__ uint32_t s_w[64 * 64];

    const int tid  = threadIdx.x;
    const int lane = tid & 31;
    const int wrp  = tid >> 5;
    const int g    = lane >> 2, tg = lane & 3;
    const int wm   = wrp & 1, wn = wrp >> 1;
    const int base = blockIdx.x * 4096;

    const int q = tid & 15;
    const float4 gam = *(const float4*)(n2g + q * 4);
    const float4 bet = *(const float4*)(n2b + q * 4);
#pragma unroll
    for (int p = 0; p < 8; ++p) {
        int m = p * 8 + (tid >> 4);
        float4 v = *(const float4*)(io + base + m * 64 + q * 4);
        float s  = v.x + v.y + v.z + v.w;
        float ss = v.x * v.x + v.y * v.y + v.z * v.z + v.w * v.w;
#pragma unroll
        for (int o = 8; o; o >>= 1) {
            s  += __shfl_xor_sync(0xffffffffu, s, o);
            ss += __shfl_xor_sync(0xffffffffu, ss, o);
        }
        float mu = s * 0.015625f;
        float rs = rsqrtf(fmaxf(ss * 0.015625f - mu * mu, 0.f) + 1e-5f);
        uint4 o4;
        o4.x = f2tf32((v.x - mu) * rs * gam.x + bet.x);
        o4.y = f2tf32((v.y - mu) * rs * gam.y + bet.y);
        o4.z = f2tf32((v.z - mu) * rs * gam.z + bet.z);
        o4.w = f2tf32((v.w - mu) * rs * gam.w + bet.w);
        *(uint4*)&s_a[m * 64 + ((q * 4) ^ (4 * (m & 7)))] = o4;
    }
    __syncthreads();

    float c2[2][4][4];
#pragma unroll
    for (int i = 0; i < 2; ++i)
#pragma unroll
        for (int j = 0; j < 4; ++j)
#pragma unroll
            for (int r = 0; r < 4; ++r) c2[i][j][r] = 0.f;

    for (int nc = 0; nc < 4; ++nc) {
#pragma unroll
        for (int p = 0; p < 8; ++p) {
            int k = p * 8 + (tid >> 4);
            float4 v = *(const float4*)(w1 + k * 256 + nc * 64 + q * 4);
            uint4 o4 = { f2tf32(v.x), f2tf32(v.y), f2tf32(v.z), f2tf32(v.w) };
            *(uint4*)&s_w[k * 64 + ((q * 4) ^ (8 * (k & 3)))] = o4;
        }
        __syncthreads();

        float f1[2][4][4];
#pragma unroll
        for (int i = 0; i < 2; ++i)
#pragma unroll
            for (int j = 0; j < 4; ++j)
#pragma unroll
                for (int r = 0; r < 4; ++r) f1[i][j][r] = 0.f;

#pragma unroll
        for (int k0 = 0; k0 < 8; ++k0) {
            uint32_t a[2][4], b[4][2];
            int kk = k0 * 8 + tg;
#pragma unroll
            for (int i = 0; i < 2; ++i) {
                int r0 = wm * 32 + i * 16 + g;
                int r1 = r0 + 8;
                a[i][0] = s_a[r0 * 64 + (kk ^ (4 * (r0 & 7)))];
                a[i][1] = s_a[r1 * 64 + (kk ^ (4 * (r1 & 7)))];
                a[i][2] = s_a[r0 * 64 + ((kk + 4) ^ (4 * (r0 & 7)))];
                a[i][3] = s_a[r1 * 64 + ((kk + 4) ^ (4 * (r1 & 7)))];
            }
#pragma unroll
            for (int j = 0; j < 4; ++j) {
                int cn = wn * 32 + j * 8 + g;
                b[j][0] = s_w[kk * 64 + (cn ^ (8 * tg))];
                b[j][1] = s_w[(kk + 4) * 64 + (cn ^ (8 * tg))];
            }
#pragma unroll
            for (int i = 0; i < 2; ++i)
#pragma unroll
                for (int j = 0; j < 4; ++j)
                    mma8(f1[i][j], a[i], b[j]);
        }

#pragma unroll
        for (int i = 0; i < 2; ++i) {
            int m0 = wm * 32 + i * 16 + g;
            int m1 = m0 + 8;
#pragma unroll
            for (int j = 0; j < 4; ++j) {
                int col0 = wn * 32 + j * 8 + tg * 2;
                float bb0 = __ldg(b1 + nc * 64 + col0);
                float bb1 = __ldg(b1 + nc * 64 + col0 + 1);
                uint2 h0, h1;
                h0.x = f2tf32(gelu_exact(f1[i][j][0] + bb0));
                h0.y = f2tf32(gelu_exact(f1[i][j][1] + bb1));
                h1.x = f2tf32(gelu_exact(f1[i][j][2] + bb0));
                h1.y = f2tf32(gelu_exact(f1[i][j][3] + bb1));
                *(uint2*)&s_h[m0 * 64 + (col0 ^ (4 * (m0 & 7)))] = h0;
                *(uint2*)&s_h[m1 * 64 + (col0 ^ (4 * (m1 & 7)))] = h1;
            }
        }
        __syncthreads();

#pragma unroll
        for (int p = 0; p < 8; ++p) {
            int k = p * 8 + (tid >> 4);
            float4 v = *(const float4*)(w2 + (nc * 64 + k) * 64 + q * 4);
            uint4 o4 = { f2tf32(v.x), f2tf32(v.y), f2tf32(v.z), f2tf32(v.w) };
            *(uint4*)&s_w[k * 64 + ((q * 4) ^ (8 * (k & 3)))] = o4;
        }
        __syncthreads();

#pragma unroll
        for (int k0 = 0; k0 < 8; ++k0) {
            uint32_t a[2][4], b[4][2];
            int kk = k0 * 8 + tg;
#pragma unroll
            for (int i = 0; i < 2; ++i) {
                int r0 = wm * 32 + i * 16 + g;
                int r1 = r0 + 8;
                a[i][0] = s_h[r0 * 64 + (kk ^ (4 * (r0 & 7)))];
                a[i][1] = s_h[r1 * 64 + (kk ^ (4 * (r1 & 7)))];
                a[i][2] = s_h[r0 * 64 + ((kk + 4) ^ (4 * (r0 & 7)))];
                a[i][3] = s_h[r1 * 64 + ((kk + 4) ^ (4 * (r1 & 7)))];
            }
#pragma unroll
            for (int j = 0; j < 4; ++j) {
                int cn = wn * 32 + j * 8 + g;
                b[j][0] = s_w[kk * 64 + (cn ^ (8 * tg))];
                b[j][1] = s_w[(kk + 4) * 64 + (cn ^ (8 * tg))];
            }
#pragma unroll
            for (int i = 0; i < 2; ++i)
#pragma unroll
                for (int j = 0; j < 4; ++j)
                    mma8(c2[i][j], a[i], b[j]);
        }
        __syncthreads();
    }

#pragma unroll
    for (int i = 0; i < 2; ++i) {
        int m0 = wm * 32 + i * 16 + g;
        int m1 = m0 + 8;
#pragma unroll
        for (int j = 0; j < 4; ++j) {
            int col = wn * 32 + j * 8 + tg * 2;
            float bb0 = __ldg(b2 + col);
            float bb1 = __ldg(b2 + col + 1);
            float2 r0 = *(const float2*)(io + base + m0 * 64 + col);
            float2 r1 = *(const float2*)(io + base + m1 * 64 + col);
            float2 o0, o1;
            o0.x = c2[i][j][0] + bb0 + r0.x;
            o0.y = c2[i][j][1] + bb1 + r0.y;
            o1.x = c2[i][j][2] + bb0 + r1.x;
            o1.y = c2[i][j][3] + bb1 + r1.y;
            *(float2*)(io + base + m0 * 64 + col) = o0;
            *(float2*)(io + base + m1 * 64 + col) = o1;
        }
    }
}

extern "C" void kernel_launch(void* const* d_in, const int* in_sizes, int n_in,
                              void* d_out, int out_size)
{
    const float* x     = (const float*)d_in[0];
    const float* n1g   = (const float*)d_in[1];
    const float* n1b   = (const float*)d_in[2];
    const float* qkvw  = (const float*)d_in[3];
    const float* qkvb  = (const float*)d_in[4];
    const float* rpb   = (const float*)d_in[5];
    const float* projw = (const float*)d_in[6];
    const float* projb = (const float*)d_in[7];
    const float* n2g   = (const float*)d_in[8];
    const float* n2b   = (const float*)d_in[9];
    const float* w1    = (const float*)d_in[10];
    const float* b1    = (const float*)d_in[11];
    const float* w2    = (const float*)d_in[12];
    const float* b2    = (const float*)d_in[13];
    float* out = (float*)d_out;

    const int attn_smem = (4096 + 4096) * 4 + 64 * 193 * 4;   // 82176 B
    cudaFuncSetAttribute(swin_attn_tc_kernel,
                         cudaFuncAttributeMaxDynamicSharedMemorySize, attn_smem);

    swin_attn_tc_kernel<<<8192, 256, attn_smem>>>(
        x, n1g, n1b, qkvw, qkvb, rpb, projw, projb, out);
    swin_mlp_tc_kernel<<<8192, 128>>>(out, n2g, n2b, w1, b1, w2, b2);
}

// round 4
// speedup vs baseline: 3.8691x; 1.3532x over previous
#include <cuda_runtime.h>
#include <cuda_bf16.h>
#include <cstdint>

// Shapes (fixed): B=2, D=H=W=64, L=262144, C=64, WS=2, S=8, NH=8, HD=8, MLP=256

__device__ __forceinline__ int rid_(int c) { return c < 62 ? 0 : (c == 62 ? 1 : 2); }

__device__ __forceinline__ uint32_t pk(float lo, float hi) {
    uint32_t r;
    asm("cvt.rn.bf16x2.f32 %0, %1, %2;" : "=r"(r) : "f"(hi), "f"(lo));
    return r;
}

__device__ __forceinline__ uint32_t s2u(const void* p) {
    return (uint32_t)__cvta_generic_to_shared(p);
}

__device__ __forceinline__ void ldsm_x4(uint32_t* r, uint32_t addr) {
    asm volatile("ldmatrix.sync.aligned.m8n8.x4.shared.b16 {%0,%1,%2,%3},[%4];"
                 : "=r"(r[0]), "=r"(r[1]), "=r"(r[2]), "=r"(r[3]) : "r"(addr));
}

__device__ __forceinline__ void ldsm_x4t(uint32_t* r, uint32_t addr) {
    asm volatile("ldmatrix.sync.aligned.m8n8.x4.trans.shared.b16 {%0,%1,%2,%3},[%4];"
                 : "=r"(r[0]), "=r"(r[1]), "=r"(r[2]), "=r"(r[3]) : "r"(addr));
}

__device__ __forceinline__ void mma16(float* d, const uint32_t* a, const uint32_t* b) {
    asm volatile(
        "mma.sync.aligned.m16n8k16.row.col.f32.bf16.bf16.f32 "
        "{%0,%1,%2,%3},{%4,%5,%6,%7},{%8,%9},{%0,%1,%2,%3};\n"
        : "+f"(d[0]), "+f"(d[1]), "+f"(d[2]), "+f"(d[3])
        : "r"(a[0]), "r"(a[1]), "r"(a[2]), "r"(a[3]), "r"(b[0]), "r"(b[1]));
}

__device__ __forceinline__ float gelu_exact(float h) {
    return 0.5f * h * (1.f + erff(h * 0.70710678118654752f));
}

// ---------------------------------------------------------------------------
// Attention kernel v3: bf16 mma + ldmatrix for QKV/proj; scalar softmax core.
// Block = 8 windows = 64 tokens, 256 threads (8 warps, warp tile 16x32).
// Dyn smem: s_a (64x128B bf16 swz) | s_w (64x128B) | s_qkv (64x193 f32)
// ---------------------------------------------------------------------------
__global__ void __launch_bounds__(256, 2) swin_attn_bf16_kernel(
    const float* __restrict__ x,
    const float* __restrict__ n1g, const float* __restrict__ n1b,
    const float* __restrict__ qkvw, const float* __restrict__ qkvb,
    const float* __restrict__ rpb,
    const float* __restrict__ projw, const float* __restrict__ projb,
    float* __restrict__ x1)
{
    extern __shared__ __align__(16) uint8_t smem[];
    uint8_t* s_a   = smem;                       // 8192 B
    uint8_t* s_w   = smem + 8192;                // 8192 B
    float*   s_qkv = (float*)(smem + 16384);     // 64*193 f32

    const int tid   = threadIdx.x;
    const int lane  = tid & 31;
    const int wrp   = tid >> 5;
    const int g     = lane >> 2, tg = lane & 3;
    const int l15   = lane & 15;
    const int hi    = lane >> 4;
    const int sw    = lane & 7;
    const int R     = (wrp & 3) << 4;            // warp row base (16)
    const int Cb    = (wrp >> 2) << 5;           // warp col base (32)

    const uint32_t ua = s2u(s_a);
    const uint32_t uw = s2u(s_w);

    // ---- Phase 1: shifted gather + LayerNorm1 -> s_a (bf16 swizzled) ----
    {
        const int m  = tid >> 2;                 // token 0..63
        const int cq = (tid & 3) << 4;           // 16 channels
        const int gwin = blockIdx.x * 8 + (m >> 3);
        const int bb   = gwin >> 15;
        const int w15  = gwin & 32767;
        const int pz = w15 >> 10, py = (w15 >> 5) & 31, px = w15 & 31;
        const int s = m & 7;
        const int dz = ((pz << 1) + (s >> 2) + 1) & 63;
        const int dy = ((py << 1) + ((s >> 1) & 1) + 1) & 63;
        const int dx = ((px << 1) + (s & 1) + 1) & 63;
        const float* src = x + (bb << 24) + ((((dz << 12) | (dy << 6) | dx)) << 6) + cq;

        float4 v[4];
        float sm = 0.f, sq = 0.f;
#pragma unroll
        for (int f = 0; f < 4; ++f) {
            v[f] = *(const float4*)(src + f * 4);
            sm += v[f].x + v[f].y + v[f].z + v[f].w;
            sq += v[f].x * v[f].x + v[f].y * v[f].y + v[f].z * v[f].z + v[f].w * v[f].w;
        }
        sm += __shfl_xor_sync(0xffffffffu, sm, 1);
        sq += __shfl_xor_sync(0xffffffffu, sq, 1);
        sm += __shfl_xor_sync(0xffffffffu, sm, 2);
        sq += __shfl_xor_sync(0xffffffffu, sq, 2);
        float mu = sm * 0.015625f;
        float rs = rsqrtf(fmaxf(sq * 0.015625f - mu * mu, 0.f) + 1e-5f);
        const int c0 = (tid & 3) << 1;           // chunk base (2 chunks of 8)
#pragma unroll
        for (int f = 0; f < 2; ++f) {
            float4 va = v[2 * f], vb = v[2 * f + 1];
            float4 g0 = *(const float4*)(n1g + cq + f * 8);
            float4 g1 = *(const float4*)(n1g + cq + f * 8 + 4);
            float4 b0 = *(const float4*)(n1b + cq + f * 8);
            float4 b1 = *(const float4*)(n1b + cq + f * 8 + 4);
            uint4 o;
            o.x = pk((va.x - mu) * rs * g0.x + b0.x, (va.y - mu) * rs * g0.y + b0.y);
            o.y = pk((va.z - mu) * rs * g0.z + b0.z, (va.w - mu) * rs * g0.w + b0.w);
            o.z = pk((vb.x - mu) * rs * g1.x + b1.x, (vb.y - mu) * rs * g1.y + b1.y);
            o.w = pk((vb.z - mu) * rs * g1.z + b1.z, (vb.w - mu) * rs * g1.w + b1.w);
            *(uint4*)(s_a + m * 128 + (((c0 + f) ^ (m & 7)) << 4)) = o;
        }
    }

    // ---- Phase 2: QKV = xn @ qkvw (3 chunks of 64) ----
    const int colB0 = ((((wrp >> 2) << 2) + 0 + hi) ^ sw) << 4;   // h=0 chunk
    const int colB1 = ((((wrp >> 2) << 2) + 2 + hi) ^ sw) << 4;   // h=1 chunk
    const uint32_t rowAoff = (uint32_t)(R + l15) * 128;

    for (int nc = 0; nc < 3; ++nc) {
        __syncthreads();
#pragma unroll
        for (int it = 0; it < 2; ++it) {
            int slot = it * 256 + tid;
            int k = slot >> 3, c = slot & 7;
            const float* p = qkvw + k * 192 + nc * 64 + c * 8;
            float4 u = *(const float4*)p;
            float4 v = *(const float4*)(p + 4);
            uint4 o = { pk(u.x, u.y), pk(u.z, u.w), pk(v.x, v.y), pk(v.z, v.w) };
            *(uint4*)(s_w + k * 128 + ((c ^ (k & 7)) << 4)) = o;
        }
        __syncthreads();

        float f1[4][4];
#pragma unroll
        for (int j = 0; j < 4; ++j)
#pragma unroll
            for (int r = 0; r < 4; ++r) f1[j][r] = 0.f;

#pragma unroll
        for (int k0 = 0; k0 < 4; ++k0) {
            uint32_t A[4], Bf[2][4];
            int colA = (((k0 << 1) + hi) ^ sw) << 4;
            ldsm_x4(A, ua + rowAoff + colA);
            uint32_t rb = uw + (uint32_t)(k0 * 2048 + l15 * 128);
            ldsm_x4t(Bf[0], rb + colB0);
            ldsm_x4t(Bf[1], rb + colB1);
#pragma unroll
            for (int j = 0; j < 4; ++j)
                mma16(f1[j], A, &Bf[j >> 1][(j & 1) * 2]);
        }

        {
            const float scale = (nc == 0) ? 0.35355339059327373f : 1.0f;
            const int m0 = R + g, m1 = m0 + 8;
#pragma unroll
            for (int j = 0; j < 4; ++j) {
                int col = Cb + j * 8 + tg * 2;
                float b0 = __ldg(qkvb + nc * 64 + col);
                float b1 = __ldg(qkvb + nc * 64 + col + 1);
                s_qkv[m0 * 193 + nc * 64 + col]     = (f1[j][0] + b0) * scale;
                s_qkv[m0 * 193 + nc * 64 + col + 1] = (f1[j][1] + b1) * scale;
                s_qkv[m1 * 193 + nc * 64 + col]     = (f1[j][2] + b0) * scale;
                s_qkv[m1 * 193 + nc * 64 + col + 1] = (f1[j][3] + b1) * scale;
            }
        }
    }
    __syncthreads();

    // ---- Phase 3: scalar attention (fp32), writes bf16 attn-out to s_a ----
#pragma unroll
    for (int r = 0; r < 2; ++r) {
        const int tk  = tid + r * 256;
        const int win = tk >> 6, hh = (tk >> 3) & 7, qi = tk & 7;
        const int gwin = blockIdx.x * 8 + win;
        const int w15  = gwin & 32767;
        const int pz = w15 >> 10, py = (w15 >> 5) & 31, px = w15 & 31;

        float q[8];
#pragma unroll
        for (int d = 0; d < 8; ++d) q[d] = s_qkv[(win * 8 + qi) * 193 + hh * 8 + d];

        int mv[8];
#pragma unroll
        for (int s = 0; s < 8; ++s) {
            int rz = rid_((pz << 1) + (s >> 2));
            int ry = rid_((py << 1) + ((s >> 1) & 1));
            int rx = rid_((px << 1) + (s & 1));
            mv[s] = rz * 9 + ry * 3 + rx;
        }
        const int mi = mv[qi];

        const int cf0p = (hh >> 1) & 1, cf1p = hh >> 2, cf2p = hh & 1;
        const int cf0q = (qi >> 1) & 1, cf1q = qi >> 2, cf2q = qi & 1;
        const int ridx = 3 * (cf0p - cf0q + 1) + (cf1p - cf1q + 1) + (cf2p - cf2q + 1);

        float sc[8];
#pragma unroll
        for (int j = 0; j < 8; ++j) {
            float a = 0.f;
#pragma unroll
            for (int d = 0; d < 8; ++d)
                a = fmaf(q[d], s_qkv[(win * 8 + j) * 193 + 64 + hh * 8 + d], a);
            a += __ldg(rpb + ridx * 8 + j);
            if (mv[j] != mi) a -= 100.f;
            sc[j] = a;
        }
        float mx = sc[0];
#pragma unroll
        for (int j = 1; j < 8; ++j) mx = fmaxf(mx, sc[j]);
        float den = 0.f;
#pragma unroll
        for (int j = 0; j < 8; ++j) { sc[j] = __expf(sc[j] - mx); den += sc[j]; }
        float inv = 1.f / den;
#pragma unroll
        for (int j = 0; j < 8; ++j) sc[j] *= inv;

        const int m = win * 8 + qi;
        float o[8];
#pragma unroll
        for (int d = 0; d < 8; ++d) {
            float acc = 0.f;
#pragma unroll
            for (int j = 0; j < 8; ++j)
                acc = fmaf(sc[j], s_qkv[(win * 8 + j) * 193 + 128 + hh * 8 + d], acc);
            o[d] = acc;
        }
        uint8_t* dst = s_a + m * 128 + ((hh ^ (m & 7)) << 4);
#pragma unroll
        for (int d = 0; d < 8; d += 2)
            *(uint32_t*)(dst + d * 2) = pk(o[d], o[d + 1]);
    }

    // stage proj weights
#pragma unroll
    for (int it = 0; it < 2; ++it) {
        int slot = it * 256 + tid;
        int k = slot >> 3, c = slot & 7;
        const float* p = projw + k * 64 + c * 8;
        float4 u = *(const float4*)p;
        float4 v = *(const float4*)(p + 4);
        uint4 o = { pk(u.x, u.y), pk(u.z, u.w), pk(v.x, v.y), pk(v.z, v.w) };
        *(uint4*)(s_w + k * 128 + ((c ^ (k & 7)) << 4)) = o;
    }
    __syncthreads();

    // ---- Phase 4: proj GEMM + window-reverse scatter + residual ----
    {
        float c2[4][4];
#pragma unroll
        for (int j = 0; j < 4; ++j)
#pragma unroll
            for (int r = 0; r < 4; ++r) c2[j][r] = 0.f;

#pragma unroll
        for (int k0 = 0; k0 < 4; ++k0) {
            uint32_t A[4], Bf[2][4];
            int colA = (((k0 << 1) + hi) ^ sw) << 4;
            ldsm_x4(A, ua + rowAoff + colA);
            uint32_t rb = uw + (uint32_t)(k0 * 2048 + l15 * 128);
            ldsm_x4t(Bf[0], rb + colB0);
            ldsm_x4t(Bf[1], rb + colB1);
#pragma unroll
            for (int j = 0; j < 4; ++j)
                mma16(c2[j], A, &Bf[j >> 1][(j & 1) * 2]);
        }

        int offr[2];
#pragma unroll
        for (int i = 0; i < 2; ++i) {
            int m = R + g + i * 8;
            int gwin = blockIdx.x * 8 + (m >> 3);
            int bb   = gwin >> 15;
            int w15  = gwin & 32767;
            int pz = w15 >> 10, py = (w15 >> 5) & 31, px = w15 & 31;
            int s = m & 7;
            int px1 = ((px & 15) << 1) | (s >> 2);
            int py1 = ((py & 15) << 1) | (px >> 4);
            int a2  = (py >> 4) & 1;
            int b2  = (s >> 1) & 1;
            int cc2 = s & 1;
            int gg = (pz << 5) + py1;
            gg = (gg << 1) + b2;
            gg = (gg << 1) + a2;
            gg = (gg << 5) + px1;
            gg = (gg << 1) + cc2;
            int dd  = ((gg >> 12) + 1) & 63;
            int hh2 = ((gg >> 6) + 1) & 63;
            int ww2 = (gg + 1) & 63;
            offr[i] = (bb << 24) + ((((dd << 12) | (hh2 << 6) | ww2)) << 6);
        }
#pragma unroll
        for (int j = 0; j < 4; ++j) {
            int col = Cb + j * 8 + tg * 2;
            float b0 = __ldg(projb + col);
            float b1 = __ldg(projb + col + 1);
#pragma unroll
            for (int i = 0; i < 2; ++i) {
                float2 rx = *(const float2*)(x + offr[i] + col);
                float2 o;
                o.x = c2[j][2 * i]     + b0 + rx.x;
                o.y = c2[j][2 * i + 1] + b1 + rx.y;
                *(float2*)(x1 + offr[i] + col) = o;
            }
        }
    }
}

// ---------------------------------------------------------------------------
// MLP kernel v3: bf16 mma + ldmatrix, 128 tokens/block, 256 threads, 8 warps.
// smem: s_a 16K | s_h 16K | s_w1 8K | s_w2 8K = 48KB
// ---------------------------------------------------------------------------
__global__ void __launch_bounds__(256, 2) swin_mlp_bf16_kernel(
    float* __restrict__ io,
    const float* __restrict__ n2g, const float* __restrict__ n2b,
    const float* __restrict__ w1, const float* __restrict__ b1,
    const float* __restrict__ w2, const float* __restrict__ b2)
{
    __shared__ __align__(16) uint8_t s_a[128 * 128];
    __shared__ __align__(16) uint8_t s_h[128 * 128];
    __shared__ __align__(16) uint8_t s_w1[64 * 128];
    __shared__ __align__(16) uint8_t s_w2[64 * 128];

    const int tid  = threadIdx.x;
    const int lane = tid & 31;
    const int wrp  = tid >> 5;
    const int g    = lane >> 2, tg = lane & 3;
    const int l15  = lane & 15;
    const int hi   = lane >> 4;
    const int sw   = lane & 7;
    const int wm   = wrp & 3;                    // 4 m-bands of 32
    const int wn   = wrp >> 2;                   // 2 n-halves of 32
    const int base = blockIdx.x * 8192;          // 128 tokens * 64 ch

    const uint32_t uaa = s2u(s_a);
    const uint32_t uhh = s2u(s_h);
    const uint32_t uw1 = s2u(s_w1);
    const uint32_t uw2 = s2u(s_w2);

    // ---- Phase 1: LayerNorm2 -> s_a (bf16 swizzled) ----
    {
        const int mb = tid >> 2;
        const int cq = (tid & 3) << 4;
        const int c0 = (tid & 3) << 1;
        float4 g0 = *(const float4*)(n2g + cq);
        float4 g1 = *(const float4*)(n2g + cq + 4);
        float4 g2 = *(const float4*)(n2g + cq + 8);
        float4 g3 = *(const float4*)(n2g + cq + 12);
        float4 e0 = *(const float4*)(n2b + cq);
        float4 e1 = *(const float4*)(n2b + cq + 4);
        float4 e2 = *(const float4*)(n2b + cq + 8);
        float4 e3 = *(const float4*)(n2b + cq + 12);
#pragma unroll
        for (int p = 0; p < 2; ++p) {
            int m = p * 64 + mb;
            const float* src = io + base + m * 64 + cq;
            float4 v[4];
            float sm = 0.f, sq = 0.f;
#pragma unroll
            for (int f = 0; f < 4; ++f) {
                v[f] = *(const float4*)(src + f * 4);
                sm += v[f].x + v[f].y + v[f].z + v[f].w;
                sq += v[f].x * v[f].x + v[f].y * v[f].y + v[f].z * v[f].z + v[f].w * v[f].w;
            }
            sm += __shfl_xor_sync(0xffffffffu, sm, 1);
            sq += __shfl_xor_sync(0xffffffffu, sq, 1);
            sm += __shfl_xor_sync(0xffffffffu, sm, 2);
            sq += __shfl_xor_sync(0xffffffffu, sq, 2);
            float mu = sm * 0.015625f;
            float rs = rsqrtf(fmaxf(sq * 0.015625f - mu * mu, 0.f) + 1e-5f);
            uint4 o;
            o.x = pk((v[0].x - mu) * rs * g0.x + e0.x, (v[0].y - mu) * rs * g0.y + e0.y);
            o.y = pk((v[0].z - mu) * rs * g0.z + e0.z, (v[0].w - mu) * rs * g0.w + e0.w);
            o.z = pk((v[1].x - mu) * rs * g1.x + e1.x, (v[1].y - mu) * rs * g1.y + e1.y);
            o.w = pk((v[1].z - mu) * rs * g1.z + e1.z, (v[1].w - mu) * rs * g1.w + e1.w);
            *(uint4*)(s_a + m * 128 + ((c0 ^ (m & 7)) << 4)) = o;
            o.x = pk((v[2].x - mu) * rs * g2.x + e2.x, (v[2].y - mu) * rs * g2.y + e2.y);
            o.y = pk((v[2].z - mu) * rs * g2.z + e2.z, (v[2].w - mu) * rs * g2.w + e2.w);
            o.z = pk((v[3].x - mu) * rs * g3.x + e3.x, (v[3].y - mu) * rs * g3.y + e3.y);
            o.w = pk((v[3].z - mu) * rs * g3.z + e3.z, (v[3].w - mu) * rs * g3.w + e3.w);
            *(uint4*)(s_a + m * 128 + (((c0 + 1) ^ (m & 7)) << 4)) = o;
        }
    }

    float c2[2][4][4];
#pragma unroll
    for (int i = 0; i < 2; ++i)
#pragma unroll
        for (int j = 0; j < 4; ++j)
#pragma unroll
            for (int r = 0; r < 4; ++r) c2[i][j][r] = 0.f;

    const int colB0 = ((wn * 4 + 0 + hi) ^ sw) << 4;
    const int colB1 = ((wn * 4 + 2 + hi) ^ sw) << 4;
    const uint32_t rowA0 = (uint32_t)(wm * 32 + l15) * 128;
    const uint32_t rowA1 = rowA0 + 16 * 128;

    for (int nc = 0; nc < 4; ++nc) {
        __syncthreads();
        // stage W1 + W2 chunks (bf16, swizzled)
#pragma unroll
        for (int it = 0; it < 2; ++it) {
            int slot = it * 256 + tid;
            int k = slot >> 3, c = slot & 7;
            int dst = k * 128 + ((c ^ (k & 7)) << 4);
            {
                const float* p = w1 + k * 256 + nc * 64 + c * 8;
                float4 u = *(const float4*)p;
                float4 v = *(const float4*)(p + 4);
                uint4 o = { pk(u.x, u.y), pk(u.z, u.w), pk(v.x, v.y), pk(v.z, v.w) };
                *(uint4*)(s_w1 + dst) = o;
            }
            {
                const float* p = w2 + (nc * 64 + k) * 64 + c * 8;
                float4 u = *(const float4*)p;
                float4 v = *(const float4*)(p + 4);
                uint4 o = { pk(u.x, u.y), pk(u.z, u.w), pk(v.x, v.y), pk(v.z, v.w) };
                *(uint4*)(s_w2 + dst) = o;
            }
        }
        __syncthreads();

        // ---- GEMM1: f1 = xn @ W1chunk ----
        float f1[2][4][4];
#pragma unroll
        for (int i = 0; i < 2; ++i)
#pragma unroll
            for (int j = 0; j < 4; ++j)
#pragma unroll
                for (int r = 0; r < 4; ++r) f1[i][j][r] = 0.f;

#pragma unroll
        for (int k0 = 0; k0 < 4; ++k0) {
            uint32_t A[2][4], Bf[2][4];
            int colA = (((k0 << 1) + hi) ^ sw) << 4;
            ldsm_x4(A[0], uaa + rowA0 + colA);
            ldsm_x4(A[1], uaa + rowA1 + colA);
            uint32_t rb = uw1 + (uint32_t)(k0 * 2048 + l15 * 128);
            ldsm_x4t(Bf[0], rb + colB0);
            ldsm_x4t(Bf[1], rb + colB1);
#pragma unroll
            for (int i = 0; i < 2; ++i)
#pragma unroll
                for (int j = 0; j < 4; ++j)
                    mma16(f1[i][j], A[i], &Bf[j >> 1][(j & 1) * 2]);
        }

        // ---- bias + GELU -> s_h (bf16 swizzled) ----
#pragma unroll
        for (int i = 0; i < 2; ++i) {
            int m0 = wm * 32 + i * 16 + g;
            int m1 = m0 + 8;
#pragma unroll
            for (int j = 0; j < 4; ++j) {
                int col0 = wn * 32 + j * 8 + tg * 2;
                float bb0 = __ldg(b1 + nc * 64 + col0);
                float bb1 = __ldg(b1 + nc * 64 + col0 + 1);
                int ch = wn * 4 + j;
                *(uint32_t*)(s_h + m0 * 128 + ((ch ^ (m0 & 7)) << 4) + tg * 4) =
                    pk(gelu_exact(f1[i][j][0] + bb0), gelu_exact(f1[i][j][1] + bb1));
                *(uint32_t*)(s_h + m1 * 128 + ((ch ^ (m1 & 7)) << 4) + tg * 4) =
                    pk(gelu_exact(f1[i][j][2] + bb0), gelu_exact(f1[i][j][3] + bb1));
            }
        }
        __syncthreads();

        // ---- GEMM2 partial: c2 += h @ W2chunk ----
#pragma unroll
        for (int k0 = 0; k0 < 4; ++k0) {
            uint32_t A[2][4], Bf[2][4];
            int colA = (((k0 << 1) + hi) ^ sw) << 4;
            ldsm_x4(A[0], uhh + rowA0 + colA);
            ldsm_x4(A[1], uhh + rowA1 + colA);
            uint32_t rb = uw2 + (uint32_t)(k0 * 2048 + l15 * 128);
            ldsm_x4t(Bf[0], rb + colB0);
            ldsm_x4t(Bf[1], rb + colB1);
#pragma unroll
            for (int i = 0; i < 2; ++i)
#pragma unroll
                for (int j = 0; j < 4; ++j)
                    mma16(c2[i][j], A[i], &Bf[j >> 1][(j & 1) * 2]);
        }
    }

    // ---- epilogue: + b2 + residual ----
#pragma unroll
    for (int i = 0; i < 2; ++i) {
        int m0 = wm * 32 + i * 16 + g;
        int m1 = m0 + 8;
#pragma unroll
        for (int j = 0; j < 4; ++j) {
            int col = wn * 32 + j * 8 + tg * 2;
            float bb0 = __ldg(b2 + col);
            float bb1 = __ldg(b2 + col + 1);
            float2 r0 = *(const float2*)(io + base + m0 * 64 + col);
            float2 r1 = *(const float2*)(io + base + m1 * 64 + col);
            float2 o0, o1;
            o0.x = c2[i][j][0] + bb0 + r0.x;
            o0.y = c2[i][j][1] + bb1 + r0.y;
            o1.x = c2[i][j][2] + bb0 + r1.x;
            o1.y = c2[i][j][3] + bb1 + r1.y;
            *(float2*)(io + base + m0 * 64 + col) = o0;
            *(float2*)(io + base + m1 * 64 + col) = o1;
        }
    }
}

extern "C" void kernel_launch(void* const* d_in, const int* in_sizes, int n_in,
                              void* d_out, int out_size)
{
    const float* x     = (const float*)d_in[0];
    const float* n1g   = (const float*)d_in[1];
    const float* n1b   = (const float*)d_in[2];
    const float* qkvw  = (const float*)d_in[3];
    const float* qkvb  = (const float*)d_in[4];
    const float* rpb   = (const float*)d_in[5];
    const float* projw = (const float*)d_in[6];
    const float* projb = (const float*)d_in[7];
    const float* n2g   = (const float*)d_in[8];
    const float* n2b   = (const float*)d_in[9];
    const float* w1    = (const float*)d_in[10];
    const float* b1    = (const float*)d_in[11];
    const float* w2    = (const float*)d_in[12];
    const float* b2    = (const float*)d_in[13];
    float* out = (float*)d_out;

    const int attn_smem = 8192 + 8192 + 64 * 193 * 4;   // 65792 B
    cudaFuncSetAttribute(swin_attn_bf16_kernel,
                         cudaFuncAttributeMaxDynamicSharedMemorySize, attn_smem);

    swin_attn_bf16_kernel<<<8192, 256, attn_smem>>>(
        x, n1g, n1b, qkvw, qkvb, rpb, projw, projb, out);
    swin_mlp_bf16_kernel<<<4096, 256>>>(out, n2g, n2b, w1, b1, w2, b2);
}